// round 1
// baseline (speedup 1.0000x reference)
#include <cuda_runtime.h>
#include <math.h>
#include <stdint.h>

// ---------------------------------------------------------------------------
// Model_25975962206896: 4-qubit VQC, B=524288.
// Z = s† (W† M W) s, s = v⊗v⊗v⊗v rank-1 ⇒ Z collapses to a 15-term
// trigonometric polynomial in (f0, f1). Setup kernel builds coefficients
// (double precision), eval kernel is pure streaming (8B in, 4B out per elem).
// ---------------------------------------------------------------------------

__device__ float g_cA[15];
__device__ float g_cB[15];

// complex-double helpers
__device__ __forceinline__ double2 cmul(double2 a, double2 b) {
    return make_double2(a.x * b.x - a.y * b.y, a.x * b.y + a.y * b.x);
}
__device__ __forceinline__ double2 cadd(double2 a, double2 b) {
    return make_double2(a.x + b.x, a.y + b.y);
}
// conj(a)*b
__device__ __forceinline__ double2 cconjmul(double2 a, double2 b) {
    return make_double2(a.x * b.x + a.y * b.y, a.x * b.y - a.y * b.x);
}

// ---------------------------------------------------------------------------
// Setup kernel: 1 block, 32 threads.
//   threads 0..23 : build the 24 RXZX 2x2 gates (3 double sincos each)
//   threads 24..29: iSWAP angle sincos
//   threads 0..15 : each owns one column of the 16x16 unitary W, applies
//                   all 6 layers, then popcount-bins rows -> S_n[i]
//   thread 0      : G[na][nb] = sum_i M_i conj(S_na[i]) S_nb[i] -> 15 coef pairs
// ---------------------------------------------------------------------------
__global__ void setup_kernel(const float* __restrict__ wU,
                             const float* __restrict__ wR) {
    __shared__ double2 gates[6][4][2][2];   // RXZX gates per layer/qubit
    __shared__ double  isc[6], iss[6];      // iSWAP cos/sin
    __shared__ double2 sW[16][16];          // sW[row i][col t]
    __shared__ double2 sS[16][5];           // popcount-binned row sums

    const int t = threadIdx.x;

    if (t < 24) {
        int l = t / 4, qb = t % 4;
        double a = (double)wR[l * 12 + qb * 3 + 0];
        double b = (double)wR[l * 12 + qb * 3 + 1];
        double c = (double)wR[l * 12 + qb * 3 + 2];
        double sa, ca, sb, cb, sc3, cc3;
        sincos(0.5 * a, &sa, &ca);
        sincos(0.5 * b, &sb, &cb);
        sincos(0.5 * c, &sc3, &cc3);
        // m1 = RX(a), m2 = RZ(b), m3 = RX(c);  g = m1 * m2 * m3
        double2 m1_00 = make_double2(ca, 0.0), m1_01 = make_double2(0.0, -sa);
        double2 m1_10 = make_double2(0.0, -sa), m1_11 = make_double2(ca, 0.0);
        double2 e0 = make_double2(cb, -sb), e1 = make_double2(cb, sb);
        double2 m3_00 = make_double2(cc3, 0.0), m3_01 = make_double2(0.0, -sc3);
        double2 m3_10 = make_double2(0.0, -sc3), m3_11 = make_double2(cc3, 0.0);
        // m23 = RZ(b)*RX(c): row0 scaled by e0, row1 by e1
        double2 m23_00 = cmul(e0, m3_00), m23_01 = cmul(e0, m3_01);
        double2 m23_10 = cmul(e1, m3_10), m23_11 = cmul(e1, m3_11);
        gates[l][qb][0][0] = cadd(cmul(m1_00, m23_00), cmul(m1_01, m23_10));
        gates[l][qb][0][1] = cadd(cmul(m1_00, m23_01), cmul(m1_01, m23_11));
        gates[l][qb][1][0] = cadd(cmul(m1_10, m23_00), cmul(m1_11, m23_10));
        gates[l][qb][1][1] = cadd(cmul(m1_10, m23_01), cmul(m1_11, m23_11));
    } else if (t < 30) {
        int l = t - 24;
        double s, c;
        sincos((double)wU[l], &s, &c);
        isc[l] = c;
        iss[l] = s;
    }
    __syncthreads();

    // Each of 16 threads builds column t of W.
    const int PAIRS[12] = {1, 2, 1, 3, 1, 2, 1, 3, 0, 3, 0, 2};
    if (t < 16) {
        for (int i = 0; i < 16; i++)
            sW[i][t] = make_double2(i == t ? 1.0 : 0.0, 0.0);
        for (int l = 0; l < 6; l++) {
            // iSWAP(theta) on qubits (p,q); qubit q lives at bit (3-q)
            int p = PAIRS[2 * l], q = PAIRS[2 * l + 1];
            int mp = 8 >> p, mq = 8 >> q;
            double c = isc[l], s = iss[l];
            for (int r = 0; r < 16; r++) {
                if (r & (mp | mq)) continue;
                int ia = r | mq;  // |01> : vp=0, vq=1
                int ib = r | mp;  // |10>
                double2 A = sW[ia][t], B = sW[ib][t];
                // new01 = c*A + i*s*B ; new10 = i*s*A + c*B
                sW[ia][t] = make_double2(c * A.x - s * B.y, c * A.y + s * B.x);
                sW[ib][t] = make_double2(c * B.x - s * A.y, c * B.y + s * A.x);
            }
            // per-qubit RXZX
            for (int qb = 0; qb < 4; qb++) {
                int mask = 8 >> qb;
                double2 g00 = gates[l][qb][0][0], g01 = gates[l][qb][0][1];
                double2 g10 = gates[l][qb][1][0], g11 = gates[l][qb][1][1];
                for (int r = 0; r < 16; r++) {
                    if (r & mask) continue;
                    double2 a0 = sW[r][t], a1 = sW[r | mask][t];
                    sW[r][t]        = cadd(cmul(g00, a0), cmul(g01, a1));
                    sW[r | mask][t] = cadd(cmul(g10, a0), cmul(g11, a1));
                }
            }
        }
    }
    __syncthreads();

    // Row-wise popcount bins: S_n[i] = sum_{a: popc(a)=n} W[i][a]
    if (t < 16) {
        double2 S[5];
        for (int n = 0; n < 5; n++) S[n] = make_double2(0.0, 0.0);
        for (int a = 0; a < 16; a++) S[__popc(a)] = cadd(S[__popc(a)], sW[t][a]);
        for (int n = 0; n < 5; n++) sS[t][n] = S[n];
    }
    __syncthreads();

    // G bins (thread 0): G[na][nb] = sum_i M_i conj(S_na[i]) S_nb[i]
    if (t == 0) {
        int k = 0;
        for (int na = 0; na < 5; na++) {
            for (int nb = na; nb < 5; nb++) {
                double2 G = make_double2(0.0, 0.0);
                for (int i = 0; i < 16; i++) {
                    double m = (i < 8) ? 1.0 : -1.0;
                    double2 pr = cconjmul(sS[i][na], sS[i][nb]);
                    G.x += m * pr.x;
                    G.y += m * pr.y;
                }
                if (na == nb) {
                    g_cA[k] = (float)G.x;
                    g_cB[k] = 0.0f;
                } else {
                    g_cA[k] = (float)(2.0 * G.x);
                    g_cB[k] = (float)(-2.0 * G.y);
                }
                k++;
            }
        }
    }
}

// ---------------------------------------------------------------------------
// Eval kernel: one thread = 2 batch elements (one float4 load, float2 store).
// ---------------------------------------------------------------------------
__device__ __forceinline__ float eval_one(float f0, float f1,
                                          const float* A, const float* B) {
    // pair k -> (na,nb): m = nb-na, p = na+nb
    const int MK[15] = {0, 1, 2, 3, 4, 0, 1, 2, 3, 0, 1, 2, 0, 1, 0};
    const int PK[15] = {0, 1, 2, 3, 4, 2, 3, 4, 5, 4, 5, 6, 6, 7, 8};
    float s, c;
    sincosf(0.5f * f1, &s, &c);
    float s1, c1;
    sincosf(f0, &s1, &c1);
    float c2 = fmaf(2.0f * c1, c1, -1.0f);
    float s2 = 2.0f * s1 * c1;
    float c3 = c2 * c1 - s2 * s1;
    float s3 = s2 * c1 + c2 * s1;
    float c4 = c3 * c1 - s3 * s1;
    float s4 = s3 * c1 + c3 * s1;
    float cm[5] = {1.0f, c1, c2, c3, c4};
    float sm[5] = {0.0f, s1, s2, s3, s4};
    float cp[9], sp[9];
    cp[0] = 1.0f;
    sp[0] = 1.0f;
#pragma unroll
    for (int i = 1; i < 9; i++) {
        cp[i] = cp[i - 1] * c;
        sp[i] = sp[i - 1] * s;
    }
    float Z = 0.0f;
#pragma unroll
    for (int k = 0; k < 15; k++) {
        float trig = fmaf(A[k], cm[MK[k]], B[k] * sm[MK[k]]);
        Z = fmaf(trig, cp[8 - PK[k]] * sp[PK[k]], Z);
    }
    return Z;
}

__global__ __launch_bounds__(256) void eval_kernel(
    const float4* __restrict__ in, const float* __restrict__ scp,
    const float* __restrict__ bip, float2* __restrict__ out) {
    float A[15], B[15];
#pragma unroll
    for (int k = 0; k < 15; k++) {
        A[k] = __ldg(&g_cA[k]);
        B[k] = __ldg(&g_cB[k]);
    }
    const float scale = __ldg(scp);
    const float bias = __ldg(bip);
    const float K = 0.011180339887f;  // sqrt(2/1000)/4

    int t = blockIdx.x * blockDim.x + threadIdx.x;
    float4 v = in[t];

    float Z0 = eval_one(v.x, v.y, A, B);
    float Z1 = eval_one(v.z, v.w, A, B);

    float2 r;
    r.x = fmaf(scale, fmaf(K, fmaf(Z0, Z0, -1.0f), Z0), bias);
    r.y = fmaf(scale, fmaf(K, fmaf(Z1, Z1, -1.0f), Z1), bias);
    out[t] = r;
}

// ---------------------------------------------------------------------------
extern "C" void kernel_launch(void* const* d_in, const int* in_sizes, int n_in,
                              void* d_out, int out_size) {
    const float* inputs = (const float*)d_in[0];  // [B,2] float32
    const float* wU     = (const float*)d_in[1];  // [6]
    const float* wR     = (const float*)d_in[2];  // [6,4,3]
    const float* sc     = (const float*)d_in[3];  // [] out_scale
    const float* bi     = (const float*)d_in[4];  // [] out_bias

    setup_kernel<<<1, 32>>>(wU, wR);

    int nthreads = out_size / 2;  // 2 elements per thread
    int blocks = (nthreads + 255) / 256;
    eval_kernel<<<blocks, 256>>>((const float4*)inputs, sc, bi,
                                 (float2*)d_out);
}

// round 3
// speedup vs baseline: 1.7451x; 1.7451x over previous
#include <cuda_runtime.h>
#include <math.h>
#include <stdint.h>

// ---------------------------------------------------------------------------
// Model_25975962206896: 4-qubit VQC, B=524288.
// Z = s† (W† M W) s with s = v⊗v⊗v⊗v rank-1 ⇒ Z collapses to a 15-term
// trigonometric polynomial in (f0, f1). Setup kernel (float, register-resident
// W columns) builds the 30 coefficients; eval kernel streams 8B in / 4B out
// per element using MUFU __sincosf.
// ---------------------------------------------------------------------------

__device__ float g_cA[15];
__device__ float g_cB[15];

__device__ __forceinline__ float2 cmulf(float2 a, float2 b) {
    return make_float2(a.x * b.x - a.y * b.y, a.x * b.y + a.y * b.x);
}
__device__ __forceinline__ float2 caddf(float2 a, float2 b) {
    return make_float2(a.x + b.x, a.y + b.y);
}

// ---------------------------------------------------------------------------
// Setup kernel: 1 block, 32 threads, all float.
//   threads 0..23 : the 24 RXZX 2x2 gates (precise sincosf, only 72 calls)
//   threads 24..29: iSWAP angle sincos
//   threads 0..15 : column t of the 16x16 unitary W, built in REGISTERS with
//                   fully unrolled layers (compile-time masks)
//   threads 0..15 : popcount row bins S_n[i]
//   threads 0..14 : one (na,nb) coefficient pair each
// ---------------------------------------------------------------------------
__global__ void setup_kernel(const float* __restrict__ wU,
                             const float* __restrict__ wR) {
    __shared__ float2 gates[6][4][2][2];
    __shared__ float  isc[6], iss[6];
    __shared__ float2 sW[16][16];   // sW[row i][col t]
    __shared__ float2 sS[16][5];    // popcount-binned row sums

    const int t = threadIdx.x;

    if (t < 24) {
        int l = t / 4, qb = t % 4;
        float a = wR[l * 12 + qb * 3 + 0];
        float b = wR[l * 12 + qb * 3 + 1];
        float c = wR[l * 12 + qb * 3 + 2];
        float sa, ca, sb, cb, sc3, cc3;
        sincosf(0.5f * a, &sa, &ca);
        sincosf(0.5f * b, &sb, &cb);
        sincosf(0.5f * c, &sc3, &cc3);
        // g = RX(a) * RZ(b) * RX(c)
        float2 m1_00 = make_float2(ca, 0.f), m1_01 = make_float2(0.f, -sa);
        float2 m1_10 = make_float2(0.f, -sa), m1_11 = make_float2(ca, 0.f);
        float2 e0 = make_float2(cb, -sb), e1 = make_float2(cb, sb);
        float2 m3_00 = make_float2(cc3, 0.f), m3_01 = make_float2(0.f, -sc3);
        float2 m3_10 = make_float2(0.f, -sc3), m3_11 = make_float2(cc3, 0.f);
        float2 m23_00 = cmulf(e0, m3_00), m23_01 = cmulf(e0, m3_01);
        float2 m23_10 = cmulf(e1, m3_10), m23_11 = cmulf(e1, m3_11);
        gates[l][qb][0][0] = caddf(cmulf(m1_00, m23_00), cmulf(m1_01, m23_10));
        gates[l][qb][0][1] = caddf(cmulf(m1_00, m23_01), cmulf(m1_01, m23_11));
        gates[l][qb][1][0] = caddf(cmulf(m1_10, m23_00), cmulf(m1_11, m23_10));
        gates[l][qb][1][1] = caddf(cmulf(m1_10, m23_01), cmulf(m1_11, m23_11));
    } else if (t < 30) {
        int l = t - 24;
        float s, c;
        sincosf(wU[l], &s, &c);
        isc[l] = c;
        iss[l] = s;
    }
    __syncthreads();

    // Build column t of W entirely in registers.
    if (t < 16) {
        float2 col[16];
#pragma unroll
        for (int i = 0; i < 16; i++)
            col[i] = make_float2(i == t ? 1.f : 0.f, 0.f);

        const int PAIRS[12] = {1, 2, 1, 3, 1, 2, 1, 3, 0, 3, 0, 2};
#pragma unroll
        for (int l = 0; l < 6; l++) {
            int p = PAIRS[2 * l], q = PAIRS[2 * l + 1];
            int mp = 8 >> p, mq = 8 >> q;
            float c = isc[l], s = iss[l];
#pragma unroll
            for (int r = 0; r < 16; r++) {
                if (r & (mp | mq)) continue;
                int ia = r | mq, ib = r | mp;
                float2 A = col[ia], B = col[ib];
                col[ia] = make_float2(c * A.x - s * B.y, c * A.y + s * B.x);
                col[ib] = make_float2(c * B.x - s * A.y, c * B.y + s * A.x);
            }
#pragma unroll
            for (int qb = 0; qb < 4; qb++) {
                int mask = 8 >> qb;
                float2 g00 = gates[l][qb][0][0], g01 = gates[l][qb][0][1];
                float2 g10 = gates[l][qb][1][0], g11 = gates[l][qb][1][1];
#pragma unroll
                for (int r = 0; r < 16; r++) {
                    if (r & mask) continue;
                    float2 a0 = col[r], a1 = col[r | mask];
                    col[r]        = caddf(cmulf(g00, a0), cmulf(g01, a1));
                    col[r | mask] = caddf(cmulf(g10, a0), cmulf(g11, a1));
                }
            }
        }
#pragma unroll
        for (int i = 0; i < 16; i++) sW[i][t] = col[i];
    }
    __syncthreads();

    // S_n[i] = sum over columns a with popcount(a)=n of W[i][a]
    if (t < 16) {
        float2 S[5];
#pragma unroll
        for (int n = 0; n < 5; n++) S[n] = make_float2(0.f, 0.f);
#pragma unroll
        for (int a = 0; a < 16; a++) {
            int n = __popc(a);
            S[n] = caddf(S[n], sW[t][a]);
        }
#pragma unroll
        for (int n = 0; n < 5; n++) sS[t][n] = S[n];
    }
    __syncthreads();

    // One coefficient pair per thread: G[na][nb] = sum_i M_i conj(S_na) S_nb
    if (t < 15) {
        const int NA[15] = {0, 0, 0, 0, 0, 1, 1, 1, 1, 2, 2, 2, 3, 3, 4};
        const int NB[15] = {0, 1, 2, 3, 4, 1, 2, 3, 4, 2, 3, 4, 3, 4, 4};
        int na = NA[t], nb = NB[t];
        float gx = 0.f, gy = 0.f;
#pragma unroll
        for (int i = 0; i < 16; i++) {
            float m = (i < 8) ? 1.f : -1.f;
            float2 a = sS[i][na], b = sS[i][nb];
            gx += m * (a.x * b.x + a.y * b.y);
            gy += m * (a.x * b.y - a.y * b.x);
        }
        if (na == nb) {
            g_cA[t] = gx;
            g_cB[t] = 0.f;
        } else {
            g_cA[t] = 2.f * gx;
            g_cB[t] = -2.f * gy;
        }
    }
}

// ---------------------------------------------------------------------------
// Eval kernel: one thread = 2 batch elements (one float4 load, float2 store).
// ---------------------------------------------------------------------------
__device__ __forceinline__ float eval_one(float f0, float f1,
                                          const float* A, const float* B) {
    // pair k -> (na,nb): m = nb-na, p = na+nb
    const int MK[15] = {0, 1, 2, 3, 4, 0, 1, 2, 3, 0, 1, 2, 0, 1, 0};
    const int PK[15] = {0, 1, 2, 3, 4, 2, 3, 4, 5, 4, 5, 6, 6, 7, 8};
    float s, c;
    __sincosf(0.5f * f1, &s, &c);
    float s1, c1;
    __sincosf(f0, &s1, &c1);
    float c2 = fmaf(2.0f * c1, c1, -1.0f);
    float s2 = 2.0f * s1 * c1;
    float c3 = fmaf(c2, c1, -s2 * s1);
    float s3 = fmaf(s2, c1, c2 * s1);
    float c4 = fmaf(c3, c1, -s3 * s1);
    float s4 = fmaf(s3, c1, c3 * s1);
    float cm[5] = {1.0f, c1, c2, c3, c4};
    float sm[5] = {0.0f, s1, s2, s3, s4};
    float cp[9], sp[9];
    cp[0] = 1.0f;
    sp[0] = 1.0f;
#pragma unroll
    for (int i = 1; i < 9; i++) {
        cp[i] = cp[i - 1] * c;
        sp[i] = sp[i - 1] * s;
    }
    float Z = 0.0f;
#pragma unroll
    for (int k = 0; k < 15; k++) {
        float trig = fmaf(A[k], cm[MK[k]], B[k] * sm[MK[k]]);
        Z = fmaf(trig, cp[8 - PK[k]] * sp[PK[k]], Z);
    }
    return Z;
}

__global__ __launch_bounds__(256) void eval_kernel(
    const float4* __restrict__ in, const float* __restrict__ scp,
    const float* __restrict__ bip, float2* __restrict__ out) {
    float A[15], B[15];
#pragma unroll
    for (int k = 0; k < 15; k++) {
        A[k] = __ldg(&g_cA[k]);
        B[k] = __ldg(&g_cB[k]);
    }
    const float scale = __ldg(scp);
    const float bias = __ldg(bip);
    const float K = 0.011180339887f;  // sqrt(2/1000)/4

    int t = blockIdx.x * blockDim.x + threadIdx.x;
    float4 v = in[t];

    float Z0 = eval_one(v.x, v.y, A, B);
    float Z1 = eval_one(v.z, v.w, A, B);

    float2 r;
    r.x = fmaf(scale, fmaf(K, fmaf(Z0, Z0, -1.0f), Z0), bias);
    r.y = fmaf(scale, fmaf(K, fmaf(Z1, Z1, -1.0f), Z1), bias);
    out[t] = r;
}

// ---------------------------------------------------------------------------
extern "C" void kernel_launch(void* const* d_in, const int* in_sizes, int n_in,
                              void* d_out, int out_size) {
    const float* inputs = (const float*)d_in[0];  // [B,2] float32
    const float* wU     = (const float*)d_in[1];  // [6]
    const float* wR     = (const float*)d_in[2];  // [6,4,3]
    const float* sc     = (const float*)d_in[3];  // [] out_scale
    const float* bi     = (const float*)d_in[4];  // [] out_bias

    setup_kernel<<<1, 32>>>(wU, wR);

    int nthreads = out_size / 2;  // 2 elements per thread
    int blocks = (nthreads + 255) / 256;
    eval_kernel<<<blocks, 256>>>((const float4*)inputs, sc, bi,
                                 (float2*)d_out);
}